// round 14
// baseline (speedup 1.0000x reference)
#include <cuda_runtime.h>
#include <cuda_bf16.h>
#include <cuda_fp16.h>
#include <cstdint>

#define MAX_N 50000
#define MAX_E 800000
#define CHUNK 256
#define MAX_CHUNKS ((MAX_N + CHUNK - 1) / CHUNK)

// ---------------- device scratch (no allocation allowed) ----------------
__device__ unsigned long long g_pk[MAX_N];      // (cnt<<40) | fixed24(w-sum)
__device__ float g_dis[MAX_N];
__device__ int   g_rowptr[MAX_N + 1];
__device__ int   g_cur[MAX_N];
__device__ int   g_csum[MAX_CHUNKS];
__device__ int2  g_epack[MAX_E];                 // (src, val bits)
__device__ __half g_hh[(size_t)MAX_N * 128];     // GEMM outputs (fp16)
__device__ __half g_x16[(size_t)MAX_N * 128];    // agg outputs (fp16, ping)
// transposed fp16 weights [FO][K]
__device__ __half g_w1t[128 * 256];
__device__ __half g_w2t[128 * 128];
__device__ __half g_w3t[64 * 128];

// ---------------- mma/ldsm helpers ----------------
__device__ __forceinline__ void mma_fp16(float* c, const uint32_t* a, const uint32_t* b) {
    asm volatile("mma.sync.aligned.m16n8k16.row.col.f32.f16.f16.f32 "
                 "{%0,%1,%2,%3}, {%4,%5,%6,%7}, {%8,%9}, {%0,%1,%2,%3};"
                 : "+f"(c[0]), "+f"(c[1]), "+f"(c[2]), "+f"(c[3])
                 : "r"(a[0]), "r"(a[1]), "r"(a[2]), "r"(a[3]),
                   "r"(b[0]), "r"(b[1]));
}

__device__ __forceinline__ void ldsm_x4(uint32_t* r, uint32_t saddr) {
    asm volatile("ldmatrix.sync.aligned.m8n8.x4.shared.b16 {%0,%1,%2,%3}, [%4];"
                 : "=r"(r[0]), "=r"(r[1]), "=r"(r[2]), "=r"(r[3]) : "r"(saddr));
}

__device__ __forceinline__ void ldsm_x2(uint32_t* r, uint32_t saddr) {
    asm volatile("ldmatrix.sync.aligned.m8n8.x2.shared.b16 {%0,%1}, [%2];"
                 : "=r"(r[0]), "=r"(r[1]) : "r"(saddr));
}

// ---------------- weight transpose to fp16 ----------------
__global__ void k_splitW(const float* __restrict__ W1, const float* __restrict__ W2,
                         const float* __restrict__ W3) {
    int i = blockIdx.x * blockDim.x + threadIdx.x;
    const int n1 = 256 * 128, n2 = 128 * 128, n3 = 128 * 64;
    if (i < n1) {
        int k = i / 128, n = i % 128;
        g_w1t[n * 256 + k] = __float2half_rn(W1[i]);
    } else if (i < n1 + n2) {
        int j = i - n1; int k = j / 128, n = j % 128;
        g_w2t[n * 128 + k] = __float2half_rn(W2[j]);
    } else if (i < n1 + n2 + n3) {
        int j = i - n1 - n2; int k = j / 64, n = j % 64;
        g_w3t[n * 128 + k] = __float2half_rn(W3[j]);
    }
}

// ---------------- CSR precompute ----------------
__global__ void k_hist(const int* __restrict__ dst, const float* __restrict__ w, int E) {
    int i = blockIdx.x * blockDim.x + threadIdx.x;
    if (i < E) {
        unsigned long long pk = (1ULL << 40)
            | (unsigned long long)__float2uint_rn(w[i] * 16777216.0f);
        atomicAdd(&g_pk[dst[i]], pk);
    }
}

__global__ void k_scanA(int N) {
    __shared__ int s[CHUNK];
    int t = threadIdx.x;
    int i = blockIdx.x * CHUNK + t;
    int v = (i < N) ? (int)(g_pk[i] >> 40) : 0;
    s[t] = v;
    __syncthreads();
#pragma unroll
    for (int off = 1; off < CHUNK; off <<= 1) {
        int x = (t >= off) ? s[t - off] : 0;
        __syncthreads();
        s[t] += x;
        __syncthreads();
    }
    if (i < N) g_rowptr[i] = s[t] - v;
    if (t == CHUNK - 1) g_csum[blockIdx.x] = s[t];
}

__global__ void k_scanC(int N, int E, int nchunks) {
    __shared__ int sc[CHUNK];
    int t = threadIdx.x;
    int v = (t < nchunks) ? g_csum[t] : 0;
    sc[t] = v;
    __syncthreads();
#pragma unroll
    for (int off = 1; off < CHUNK; off <<= 1) {
        int x = (t >= off) ? sc[t - off] : 0;
        __syncthreads();
        sc[t] += x;
        __syncthreads();
    }
    int i = blockIdx.x * blockDim.x + t;
    if (i < N) {
        int c = i >> 8;
        int off = (c == 0) ? 0 : sc[c - 1];
        int r = g_rowptr[i] + off;
        g_rowptr[i] = r;
        g_cur[i] = r;
        float degw = (float)(g_pk[i] & ((1ULL << 40) - 1)) * (1.0f / 16777216.0f);
        g_dis[i] = rsqrtf(degw + 1.0f);   // self-loop weight 1
    }
    if (i == 0) g_rowptr[N] = E;
}

__global__ void k_fill(const int* __restrict__ src, const int* __restrict__ dst,
                       const float* __restrict__ w, int E) {
    int e = blockIdx.x * blockDim.x + threadIdx.x;
    if (e >= E) return;
    int d = dst[e];
    int s = src[e];
    int pos = atomicAdd(&g_cur[d], 1);
    int2 pk;
    pk.x = s;
    pk.y = __float_as_int(w[e] * g_dis[s]);   // dis[dst] factored into epilogue
    g_epack[pos] = pk;
}

// ---------------- fp16 tensor-core GEMM (m16n8k16) ----------------
// H[N,FO] = X[N,K] @ W[K,FO]; W transposed fp16 [FO][K]; output fp16.
// IN_F32: X is fp32 (layer 1) else fp16.
template<int K, int FO, bool IN_F32>
__global__ __launch_bounds__(256)
void k_gemm_f16(const void* __restrict__ Xv,
                const __half* __restrict__ Wt,
                __half* __restrict__ H, int N) {
    constexpr int BM = 128, BK = 32;
    constexpr int AP = BK + 8;            // 40 halves = 80B row stride
    constexpr int NF = FO / 16;
    __shared__ __half As[BM * AP];
    __shared__ __half Ws[FO * AP];

    const int tid = threadIdx.x;
    const int lane = tid & 31, wid = tid >> 5;
    const int g = lane >> 2, t = lane & 3;
    const int warp_m = (wid & 3) * 32;
    const int warp_n = (wid >> 2) * (FO / 2);
    const int m0 = blockIdx.x * BM;

    const uint32_t as_b = (uint32_t)__cvta_generic_to_shared(As);
    const uint32_t ws_b = (uint32_t)__cvta_generic_to_shared(Ws);

    const int a_grp = lane >> 3, a_r8 = lane & 7;
    const int b_r8 = lane & 7, b_half = (lane >> 3) & 1;

    float acc[2][NF][4];
#pragma unroll
    for (int mf = 0; mf < 2; mf++)
#pragma unroll
        for (int nf = 0; nf < NF; nf++)
#pragma unroll
            for (int i = 0; i < 4; i++) acc[mf][nf][i] = 0.0f;

    for (int k0 = 0; k0 < K; k0 += BK) {
        // ---- A tile ----
        if constexpr (IN_F32) {
            const float* X = (const float*)Xv;
#pragma unroll
            for (int it = 0; it < 4; it++) {
                int f4 = tid + it * 256;
                int row = f4 >> 3;
                int kg = (f4 & 7) << 2;
                float4 v = make_float4(0.f, 0.f, 0.f, 0.f);
                if (m0 + row < N) v = *(const float4*)(X + (size_t)(m0 + row) * K + k0 + kg);
                __half2 h0 = __floats2half2_rn(v.x, v.y);
                __half2 h1 = __floats2half2_rn(v.z, v.w);
                uint2 pk;
                pk.x = *(uint32_t*)&h0;
                pk.y = *(uint32_t*)&h1;
                *(uint2*)(As + row * AP + kg) = pk;
            }
        } else {
            const __half* X = (const __half*)Xv;
#pragma unroll
            for (int it = 0; it < 2; it++) {
                int u = tid + it * 256;
                int row = u >> 2;
                int kg = (u & 3) << 3;
                uint4 v = make_uint4(0, 0, 0, 0);
                if (m0 + row < N) v = *(const uint4*)(X + (size_t)(m0 + row) * K + k0 + kg);
                *(uint4*)(As + row * AP + kg) = v;
            }
        }
        // ---- W tile: [FO][BK] fp16 ----
        constexpr int WIT = FO * BK / 8 / 256;   // 2 (FO=128) or 1 (FO=64)
#pragma unroll
        for (int it = 0; it < WIT; it++) {
            int u = tid + it * 256;
            int n = u >> 2;
            int kg = (u & 3) << 3;
            *(uint4*)(Ws + n * AP + kg) = *(const uint4*)(Wt + (size_t)n * K + k0 + kg);
        }
        __syncthreads();

#pragma unroll
        for (int ks = 0; ks < 2; ks++) {
            const int kb = ks * 16;
            uint32_t a[2][4];
#pragma unroll
            for (int mf = 0; mf < 2; mf++) {
                uint32_t off = ((warp_m + mf * 16 + (a_grp & 1) * 8 + a_r8) * AP
                                + kb + (a_grp >> 1) * 8) * 2;
                ldsm_x4(a[mf], as_b + off);
            }
#pragma unroll
            for (int nf = 0; nf < NF; nf++) {
                uint32_t boff = ((warp_n + nf * 8 + b_r8) * AP + kb + b_half * 8) * 2;
                uint32_t b[2];
                ldsm_x2(b, ws_b + boff);
#pragma unroll
                for (int mf = 0; mf < 2; mf++) {
                    mma_fp16(acc[mf][nf], a[mf], b);
                }
            }
        }
        __syncthreads();
    }

#pragma unroll
    for (int mf = 0; mf < 2; mf++) {
        int r0 = m0 + warp_m + mf * 16 + g;
#pragma unroll
        for (int nf = 0; nf < NF; nf++) {
            int col = warp_n + nf * 8 + 2 * t;
            if (r0 < N)
                *(__half2*)(H + (size_t)r0 * FO + col) =
                    __floats2half2_rn(acc[mf][nf][0], acc[mf][nf][1]);
            if (r0 + 8 < N)
                *(__half2*)(H + (size_t)(r0 + 8) * FO + col) =
                    __floats2half2_rn(acc[mf][nf][2], acc[mf][nf][3]);
        }
    }
}

// ---------------- fused CSR gather (fp16 H) + self-loop + bias + ReLU -> fp16 ----------------
__device__ __forceinline__ void acc_row128(float4& acc, float v, uint2 r) {
    float2 a0 = __half22float2(*(__half2*)&r.x);
    float2 a1 = __half22float2(*(__half2*)&r.y);
    acc.x += v * a0.x; acc.y += v * a0.y;
    acc.z += v * a1.x; acc.w += v * a1.y;
}

__global__ __launch_bounds__(256)
void k_agg128h(const __half* __restrict__ H, const float* __restrict__ bias,
               __half* __restrict__ Out, int N) {
    int node = (blockIdx.x * blockDim.x + threadIdx.x) >> 5;
    if (node >= N) return;
    int lane = threadIdx.x & 31;
    int beg = g_rowptr[node];
    int end = g_rowptr[node + 1];

    float4 acc = make_float4(0.f, 0.f, 0.f, 0.f);
    int j = beg;
    for (; j + 3 < end; j += 4) {
        int2 p0 = __ldg(&g_epack[j]);
        int2 p1 = __ldg(&g_epack[j + 1]);
        int2 p2 = __ldg(&g_epack[j + 2]);
        int2 p3 = __ldg(&g_epack[j + 3]);
        uint2 r0 = *(const uint2*)(H + (size_t)p0.x * 128 + lane * 4);
        uint2 r1 = *(const uint2*)(H + (size_t)p1.x * 128 + lane * 4);
        uint2 r2 = *(const uint2*)(H + (size_t)p2.x * 128 + lane * 4);
        uint2 r3 = *(const uint2*)(H + (size_t)p3.x * 128 + lane * 4);
        acc_row128(acc, __int_as_float(p0.y), r0);
        acc_row128(acc, __int_as_float(p1.y), r1);
        acc_row128(acc, __int_as_float(p2.y), r2);
        acc_row128(acc, __int_as_float(p3.y), r3);
    }
    for (; j < end; j++) {
        int2 p0 = __ldg(&g_epack[j]);
        uint2 r0 = *(const uint2*)(H + (size_t)p0.x * 128 + lane * 4);
        acc_row128(acc, __int_as_float(p0.y), r0);
    }

    float d = g_dis[node];
    float dd = d * d;
    uint2 rs = *(const uint2*)(H + (size_t)node * 128 + lane * 4);
    float2 s0 = __half22float2(*(__half2*)&rs.x);
    float2 s1 = __half22float2(*(__half2*)&rs.y);
    float4 b = *(const float4*)(bias + lane * 4);
    float4 o;
    o.x = fmaf(d, acc.x, fmaf(dd, s0.x, b.x));
    o.y = fmaf(d, acc.y, fmaf(dd, s0.y, b.y));
    o.z = fmaf(d, acc.z, fmaf(dd, s1.x, b.z));
    o.w = fmaf(d, acc.w, fmaf(dd, s1.y, b.w));
    o.x = fmaxf(o.x, 0.f); o.y = fmaxf(o.y, 0.f);
    o.z = fmaxf(o.z, 0.f); o.w = fmaxf(o.w, 0.f);
    __half2 q0 = __floats2half2_rn(o.x, o.y);
    __half2 q1 = __floats2half2_rn(o.z, o.w);
    uint2 pk;
    pk.x = *(uint32_t*)&q0;
    pk.y = *(uint32_t*)&q1;
    *(uint2*)(Out + (size_t)node * 128 + lane * 4) = pk;
}

// fp16 H, 64-wide, no ReLU, fp32 output (final layer)
__global__ __launch_bounds__(256)
void k_agg64h(const __half* __restrict__ H, const float* __restrict__ bias,
              float* __restrict__ Out, int N) {
    int node = (blockIdx.x * blockDim.x + threadIdx.x) >> 5;
    if (node >= N) return;
    int lane = threadIdx.x & 31;
    int beg = g_rowptr[node];
    int end = g_rowptr[node + 1];

    float2 acc = make_float2(0.f, 0.f);
    int j = beg;
    for (; j + 3 < end; j += 4) {
        int2 p0 = __ldg(&g_epack[j]);
        int2 p1 = __ldg(&g_epack[j + 1]);
        int2 p2 = __ldg(&g_epack[j + 2]);
        int2 p3 = __ldg(&g_epack[j + 3]);
        float2 h0 = __half22float2(*(const __half2*)(H + (size_t)p0.x * 64 + lane * 2));
        float2 h1 = __half22float2(*(const __half2*)(H + (size_t)p1.x * 64 + lane * 2));
        float2 h2 = __half22float2(*(const __half2*)(H + (size_t)p2.x * 64 + lane * 2));
        float2 h3 = __half22float2(*(const __half2*)(H + (size_t)p3.x * 64 + lane * 2));
        float v0 = __int_as_float(p0.y), v1 = __int_as_float(p1.y);
        float v2 = __int_as_float(p2.y), v3 = __int_as_float(p3.y);
        acc.x += v0 * h0.x + v1 * h1.x + v2 * h2.x + v3 * h3.x;
        acc.y += v0 * h0.y + v1 * h1.y + v2 * h2.y + v3 * h3.y;
    }
    for (; j < end; j++) {
        int2 p0 = __ldg(&g_epack[j]);
        float v0 = __int_as_float(p0.y);
        float2 h0 = __half22float2(*(const __half2*)(H + (size_t)p0.x * 64 + lane * 2));
        acc.x += v0 * h0.x; acc.y += v0 * h0.y;
    }

    float d = g_dis[node];
    float dd = d * d;
    float2 hs = __half22float2(*(const __half2*)(H + (size_t)node * 64 + lane * 2));
    float2 b = *(const float2*)(bias + lane * 2);
    float2 o;
    o.x = fmaf(d, acc.x, fmaf(dd, hs.x, b.x));
    o.y = fmaf(d, acc.y, fmaf(dd, hs.y, b.y));
    *(float2*)(Out + (size_t)node * 64 + lane * 2) = o;
}

// ---------------- launch ----------------
extern "C" void kernel_launch(void* const* d_in, const int* in_sizes, int n_in,
                              void* d_out, int out_size) {
    const float* x  = (const float*)d_in[0];
    const int*   ei = (const int*)d_in[1];
    const float* ew = (const float*)d_in[2];
    const float* W1 = (const float*)d_in[3];
    const float* b1 = (const float*)d_in[4];
    const float* W2 = (const float*)d_in[5];
    const float* b2 = (const float*)d_in[6];
    const float* W3 = (const float*)d_in[7];
    const float* b3 = (const float*)d_in[8];
    float* out = (float*)d_out;

    const int N = in_sizes[0] / 256;
    const int E = in_sizes[2];
    const int* src = ei;
    const int* dst = ei + E;

    __half* ghh;  cudaGetSymbolAddress((void**)&ghh,  g_hh);
    __half* gx16; cudaGetSymbolAddress((void**)&gx16, g_x16);
    unsigned long long* gpk; cudaGetSymbolAddress((void**)&gpk, g_pk);
    __half* w1t; cudaGetSymbolAddress((void**)&w1t, g_w1t);
    __half* w2t; cudaGetSymbolAddress((void**)&w2t, g_w2t);
    __half* w3t; cudaGetSymbolAddress((void**)&w3t, g_w3t);

    const int T = 256;
    auto cdiv = [](int a, int b) { return (a + b - 1) / b; };
    const int nchunks = cdiv(N, CHUNK);

    static cudaStream_t s2 = nullptr;
    static cudaEvent_t evF = nullptr, evJ = nullptr;
    if (s2 == nullptr) {
        cudaStreamCreateWithFlags(&s2, cudaStreamNonBlocking);
        cudaEventCreateWithFlags(&evF, cudaEventDisableTiming);
        cudaEventCreateWithFlags(&evJ, cudaEventDisableTiming);
    }

    // ---- fork: CSR build on s2, weights+GEMM1 on default ----
    cudaEventRecord(evF, 0);
    cudaStreamWaitEvent(s2, evF, 0);

    cudaMemsetAsync(gpk, 0, N * sizeof(unsigned long long), s2);
    k_hist<<<cdiv(E, T), T, 0, s2>>>(dst, ew, E);
    k_scanA<<<nchunks, CHUNK, 0, s2>>>(N);
    k_scanC<<<cdiv(N, T), T, 0, s2>>>(N, E, nchunks);
    k_fill<<<cdiv(E, T), T, 0, s2>>>(src, dst, ew, E);

    const int wtot = 256 * 128 + 128 * 128 + 128 * 64;
    k_splitW<<<cdiv(wtot, T), T>>>(W1, W2, W3);

    const int gemm_blocks = cdiv(N, 128);
    const int agg_blocks = cdiv(N * 32, T);

    k_gemm_f16<256, 128, true><<<gemm_blocks, 256>>>(x, w1t, ghh, N);

    // ---- join ----
    cudaEventRecord(evJ, s2);
    cudaStreamWaitEvent(0, evJ, 0);

    k_agg128h<<<agg_blocks, T>>>(ghh, b1, gx16, N);

    k_gemm_f16<128, 128, false><<<gemm_blocks, 256>>>(gx16, w2t, ghh, N);
    k_agg128h<<<agg_blocks, T>>>(ghh, b2, gx16, N);

    k_gemm_f16<128, 64, false><<<gemm_blocks, 256>>>(gx16, w3t, ghh, N);
    k_agg64h<<<agg_blocks, T>>>(ghh, b3, out, N);
}